// round 7
// baseline (speedup 1.0000x reference)
#include <cuda_runtime.h>
#include <cuda_fp16.h>
#include <stdint.h>

#define BB 2
#define NN 512
#define HH 128
#define DD 128
#define TT 8
#define ZK 256
#define JC 8      // sender (x) chunks
#define TJ 64     // senders per chunk
#define TY 64     // receivers (y) per CTA tile

// ---------------- device scratch ------------------------------------------
__device__ float d_A1[BB*NN*DD];    // z@Wm1 + bm1 + bme + (g@Wmg + bmg)
__device__ float d_A2[BB*NN*DD];    // z@Wm2 + bm2
__device__ float d_O1[BB*NN*DD];    // z@Wo1 + bo1
__device__ float d_P1[BB*NN*TT];    // z@Wt1 + bt1 + bte + (g@Wtg + btg)
__device__ float d_P2[BB*NN*TT];    // z@Wt2 + bt2
__device__ float d_pmax[BB*JC*NN*DD];   // partial masked maxes, 4 MB

// ---------------- helpers ----------------------------------------------------
__device__ __forceinline__ uint32_t smem_u32(const void* p) {
    uint32_t a;
    asm("{ .reg .u64 t; cvta.to.shared.u64 t, %1; cvt.u32.u64 %0, t; }"
        : "=r"(a) : "l"(p));
    return a;
}
__device__ __forceinline__ void cp16(uint32_t s, const void* g) {
    asm volatile("cp.async.cg.shared.global [%0], [%1], 16;"
                 :: "r"(s), "l"(__cvta_generic_to_global(g)));
}
#define CP_COMMIT() asm volatile("cp.async.commit_group;" ::: "memory")
#define CP_WAIT(N)  asm volatile("cp.async.wait_group %0;" :: "n"(N) : "memory")

#define MMA4(acc, a0, a1, a2, a3, b0, b1)                                   \
    asm volatile("mma.sync.aligned.m16n8k16.row.col.f32.f16.f16.f32 "       \
                 "{%0,%1,%2,%3}, {%4,%5,%6,%7}, {%8,%9}, {%0,%1,%2,%3};"    \
                 : "+f"((acc)[0]), "+f"((acc)[1]), "+f"((acc)[2]), "+f"((acc)[3]) \
                 : "r"(a0), "r"(a1), "r"(a2), "r"(a3), "r"(b0), "r"(b1))

#define FFMA2(acc, a, b) \
    asm("fma.rn.f32x2 %0, %1, %2, %0;" : "+l"(acc) : "l"(a), "l"(b))
#define PACK2(dst, v) \
    asm("mov.b64 %0, {%1, %1};" : "=l"(dst) : "f"(v))
#define UNPACK2(lo, hi, v) \
    asm("mov.b64 {%0, %1}, %2;" : "=f"(lo), "=f"(hi) : "l"(v))

// ---------------- per-node linears (graph projections folded in) -------------
__global__ __launch_bounds__(256) void k_node(
    const float* __restrict__ node, const float* __restrict__ hidden,
    const float* __restrict__ gf,
    const float* __restrict__ Wm1, const float* __restrict__ bm1,
    const float* __restrict__ Wm2, const float* __restrict__ bm2,
    const float* __restrict__ Wo1, const float* __restrict__ bo1,
    const float* __restrict__ Wt1, const float* __restrict__ bt1,
    const float* __restrict__ Wt2, const float* __restrict__ bt2,
    const float* __restrict__ Wme_b, const float* __restrict__ Wmg,
    const float* __restrict__ bmg,
    const float* __restrict__ Wtg, const float* __restrict__ bte,
    const float* __restrict__ btg)
{
    __shared__ float zt[8][ZK];
    __shared__ float gG[128];
    __shared__ float gGt[8];
    const int tid = threadIdx.x;
    const int g0 = blockIdx.x * 8;
    const int b = g0 >> 9;                 // all 8 rows share one batch
    for (int idx = tid; idx < 8*ZK; idx += 256) {
        int r = idx >> 8, c = idx & 255;
        size_t gid = (size_t)(g0 + r);
        zt[r][c] = (c < HH) ? node[gid*HH + c] : hidden[gid*HH + (c - HH)];
    }
    if (tid < 128) {                       // graph proj (msg): g@Wmg + bme + bmg
        float s = 0.f;
        #pragma unroll 4
        for (int h = 0; h < HH; ++h) s = fmaf(gf[b*HH + h], Wmg[h*DD + tid], s);
        gG[tid] = s + Wme_b[tid] + bmg[tid];
    } else if (tid < 136) {                // graph proj (tri): g@Wtg + bte + btg
        int tt = tid - 128;
        float s = 0.f;
        #pragma unroll 4
        for (int h = 0; h < HH; ++h) s = fmaf(gf[b*HH + h], Wtg[h*TT + tt], s);
        gGt[tt] = s + bte[tt] + btg[tt];
    }
    __syncthreads();
    const int d = tid & 127, nh = tid >> 7;
    float s1[4] = {0,0,0,0}, s2[4] = {0,0,0,0}, so[4] = {0,0,0,0};
    #pragma unroll 4
    for (int k = 0; k < ZK; ++k) {
        float w1 = Wm1[k*DD + d], w2 = Wm2[k*DD + d], wo = Wo1[k*DD + d];
        #pragma unroll
        for (int r = 0; r < 4; ++r) {
            float z = zt[nh*4 + r][k];
            s1[r] = fmaf(z, w1, s1[r]);
            s2[r] = fmaf(z, w2, s2[r]);
            so[r] = fmaf(z, wo, so[r]);
        }
    }
    #pragma unroll
    for (int r = 0; r < 4; ++r) {
        int gid = g0 + nh*4 + r;
        d_A1[(size_t)gid*DD + d] = s1[r] + bm1[d] + gG[d];
        d_A2[(size_t)gid*DD + d] = s2[r] + bm2[d];
        d_O1[(size_t)gid*DD + d] = so[r] + bo1[d];
    }
    if (tid < 128) {
        int r = tid >> 4, tt = (tid >> 1) & 7, which = tid & 1;
        const float* W = which ? Wt2 : Wt1;
        float s = 0.f;
        #pragma unroll 4
        for (int k = 0; k < ZK; ++k) s = fmaf(zt[r][k], W[k*TT + tt], s);
        int gid = g0 + r;
        if (which) d_P2[gid*TT + tt] = s + bt2[tt];
        else       d_P1[gid*TT + tt] = s + bt1[tt] + gGt[tt];
    }
}

// ---------------- dummy (profiling slot alignment) ---------------------------
__global__ void k_dummy() {}

// ---------------- fused edge pass --------------------------------------------
// hybrid: 12 warps mma.sync (cols 0..95 + tri), 4 warps SIMT f32x2 (cols 96..127)
// smem layout (bytes)
#define FSLOT   33792                       // 64 rows * 528 B (132-float stride)
#define OFF_F   0                           // 3 fp32 edge bufs      101376
#define OFF_SA  101376                      // 2 fp16 bufs 64x272B    34816
#define OFF_WF  136192                      // fp32 W cols 96..127 [k][32] 16384
#define OFF_WTRI 152576                     // fp16 Wte [t][128]       2048
#define OFF_C   154624                      // 3 const slots x 1024    3072
#define OFF_SA1 157696                      // fp32 A1 [64][132]      33792
#define SMEM_EDGE 191488

__device__ __forceinline__ void stage_tile(
    uint32_t sb, int slot, int tid, const float* __restrict__ edge,
    const float* __restrict__ adjp, int b, int x, int y0)
{
    uint32_t fb = sb + OFF_F + (uint32_t)slot * FSLOT;
    const float* ep = edge + (((size_t)b*NN + x)*NN + y0)*DD;
    #pragma unroll
    for (int i = 0; i < 4; ++i) {
        int c = tid + i*512;
        cp16(fb + (uint32_t)(c >> 5)*528u + (uint32_t)(c & 31)*16u, ep + c*4);
    }
    if (tid < 50) {
        uint32_t cb = sb + OFF_C + (uint32_t)slot * 1024u;
        const float* src;
        if (tid < 32)      src = d_A2 + ((size_t)b*NN + x)*DD + tid*4;
        else if (tid < 48) src = adjp + ((size_t)b*NN + x)*NN + y0 + (tid-32)*4;
        else               src = d_P2 + ((size_t)b*NN + x)*TT + (tid-48)*4;
        cp16(cb + tid*16, src);
    }
}

__device__ __forceinline__ void convert_tile(char* smem, int tid, int fslot, int aslot)
{
    const char* src = smem + OFF_F + fslot*FSLOT + (tid >> 3)*528 + (tid & 7)*64;
    float4 v0 = *reinterpret_cast<const float4*>(src);
    float4 v1 = *reinterpret_cast<const float4*>(src + 16);
    float4 v2 = *reinterpret_cast<const float4*>(src + 32);
    float4 v3 = *reinterpret_cast<const float4*>(src + 48);
    __half2 h0 = __floats2half2_rn(v0.x, v0.y), h1 = __floats2half2_rn(v0.z, v0.w);
    __half2 h2 = __floats2half2_rn(v1.x, v1.y), h3 = __floats2half2_rn(v1.z, v1.w);
    __half2 h4 = __floats2half2_rn(v2.x, v2.y), h5 = __floats2half2_rn(v2.z, v2.w);
    __half2 h6 = __floats2half2_rn(v3.x, v3.y), h7 = __floats2half2_rn(v3.z, v3.w);
    uint4 o0, o1;
    o0.x = *reinterpret_cast<uint32_t*>(&h0); o0.y = *reinterpret_cast<uint32_t*>(&h1);
    o0.z = *reinterpret_cast<uint32_t*>(&h2); o0.w = *reinterpret_cast<uint32_t*>(&h3);
    o1.x = *reinterpret_cast<uint32_t*>(&h4); o1.y = *reinterpret_cast<uint32_t*>(&h5);
    o1.z = *reinterpret_cast<uint32_t*>(&h6); o1.w = *reinterpret_cast<uint32_t*>(&h7);
    char* dst = smem + OFF_SA + aslot*17408 + (tid >> 3)*272 + (tid & 7)*32;
    *reinterpret_cast<uint4*>(dst)      = o0;
    *reinterpret_cast<uint4*>(dst + 16) = o1;
}

__global__ __launch_bounds__(512, 1) void k_edge(
    const float* __restrict__ edge, const float* __restrict__ adjp,
    const float* __restrict__ Wme, const float* __restrict__ Wte,
    float* __restrict__ out_tri)
{
    extern __shared__ char smem[];
    const uint32_t sb = smem_u32(smem);
    float* sA1   = reinterpret_cast<float*>(smem + OFF_SA1);
    __half* sWtri = reinterpret_cast<__half*>(smem + OFF_WTRI);
    float* sWf   = reinterpret_cast<float*>(smem + OFF_WF);

    const int tid = threadIdx.x;
    const int w = tid >> 5, lane = tid & 31;
    const int m0 = (w & 3) * 16;          // m-tile base row
    const int cg = w >> 2;                // 0..2 = mma col-groups, 3 = SIMT warps
    const int g = lane >> 2, tig = lane & 3;
    const int xc = blockIdx.x, yt = blockIdx.y, b = blockIdx.z;
    const int y0 = yt * TY;
    const int x0 = xc * TJ;

    // ---- one-time: A1 -> smem (stride 132) ----
    {
        const float4* a1src = reinterpret_cast<const float4*>(d_A1 + ((size_t)b*NN + y0)*DD);
        #pragma unroll
        for (int i = 0; i < 4; ++i) {
            int idx = tid + i*512;
            float4 v = a1src[idx];
            *reinterpret_cast<float4*>(&sA1[(idx >> 5)*132 + (idx & 31)*4]) = v;
        }
    }
    // ---- one-time: tri weights fp16 [t][k] ----
    {
        int t = tid >> 6, k = (tid & 63) * 2;
        __half2 h = __floats2half2_rn(Wte[k*TT + t], Wte[(k+1)*TT + t]);
        *reinterpret_cast<__half2*>(&sWtri[t*128 + k]) = h;
    }
    // ---- one-time: SIMT weights fp32, cols 96..127: sWf[k][32] ----
    for (int idx = tid; idx < 128*32; idx += 512) {
        int k = idx >> 5, c = idx & 31;
        sWf[k*32 + c] = Wme[k*DD + 96 + c];
    }
    // ---- one-time: B fragments (mma warps, cols cg*32..+31) ----
    uint32_t Br[8][4][2];
    if (cg < 3) {
        const int nb = cg*32 + g;
        #pragma unroll
        for (int ks = 0; ks < 8; ++ks) {
            const int k0 = ks*16 + 2*tig;
            #pragma unroll
            for (int t = 0; t < 4; ++t) {
                const int n = nb + t*8;
                __half2 lo = __floats2half2_rn(Wme[k0*DD + n],     Wme[(k0+1)*DD + n]);
                __half2 hi = __floats2half2_rn(Wme[(k0+8)*DD + n], Wme[(k0+9)*DD + n]);
                Br[ks][t][0] = *reinterpret_cast<uint32_t*>(&lo);
                Br[ks][t][1] = *reinterpret_cast<uint32_t*>(&hi);
            }
        }
    }
    // ---- one-time: P1 regs (tri handled by cg==0 warps) ----
    float p1[4] = {0,0,0,0};
    if (cg == 0) {
        const size_t r0 = ((size_t)b*NN + y0 + m0 + g)*TT;
        p1[0] = d_P1[r0 + 2*tig];           p1[1] = d_P1[r0 + 2*tig + 1];
        p1[2] = d_P1[r0 + 8*TT + 2*tig];    p1[3] = d_P1[r0 + 8*TT + 2*tig + 1];
    }

    float rmax[16];
    #pragma unroll
    for (int i = 0; i < 16; ++i) rmax[i] = __int_as_float(0xff800000);

    const uint32_t ldmb0 = sb + OFF_SA
        + (uint32_t)(m0 + ((lane >> 3) & 1)*8 + (lane & 7)) * 272u
        + (uint32_t)((lane >> 4) & 1) * 16u;

    // SIMT lane mapping
    const int yq = lane >> 3;             // 0..3 (4 rows each)
    const int dq = lane & 7;              // 0..7 (4 cols each)
    const int dcol = 96 + dq*4;

    // ---- prologue: stage tiles 0 and 1 ----
    stage_tile(sb, 0, tid, edge, adjp, b, x0,     y0); CP_COMMIT();
    stage_tile(sb, 1, tid, edge, adjp, b, x0 + 1, y0); CP_COMMIT();
    CP_WAIT(1);
    __syncthreads();
    convert_tile(smem, tid, 0, 0);

    int fs = 0;                            // fslot of current tile = jx % 3
    for (int jx = 0; jx < TJ; ++jx) {
        CP_WAIT(0);
        __syncthreads();                   // sA[jx&1] + fbuf[(jx+1)%3] + consts ready

        const float* cs = reinterpret_cast<const float*>(smem + OFF_C) + fs*256;

        if (cg < 3) {
            // ---------- mma path ----------
            float acc[4][4] = {{0,0,0,0},{0,0,0,0},{0,0,0,0},{0,0,0,0}};
            float acct[4] = {0,0,0,0};
            const uint32_t ldmb = ldmb0 + (uint32_t)(jx & 1)*17408u;
            #pragma unroll
            for (int ks = 0; ks < 8; ++ks) {
                uint32_t a0, a1, a2, a3;
                asm volatile("ldmatrix.sync.aligned.m8n8.x4.shared.b16 {%0,%1,%2,%3}, [%4];"
                             : "=r"(a0), "=r"(a1), "=r"(a2), "=r"(a3)
                             : "r"(ldmb + (uint32_t)ks*32u));
                #pragma unroll
                for (int t = 0; t < 4; ++t)
                    MMA4(acc[t], a0, a1, a2, a3, Br[ks][t][0], Br[ks][t][1]);
                if (cg == 0) {
                    uint32_t b0 = *reinterpret_cast<const uint32_t*>(&sWtri[g*128 + ks*16 + 2*tig]);
                    uint32_t b1 = *reinterpret_cast<const uint32_t*>(&sWtri[g*128 + ks*16 + 2*tig + 8]);
                    MMA4(acct, a0, a1, a2, a3, b0, b1);
                }
            }
            const float aj0 = cs[128 + m0 + g];
            const float aj1 = cs[128 + m0 + 8 + g];
            #pragma unroll
            for (int t = 0; t < 4; ++t) {
                const int c = cg*32 + t*8 + 2*tig;
                float2 a2v = *reinterpret_cast<const float2*>(&cs[c]);
                float2 u0  = *reinterpret_cast<const float2*>(&sA1[(m0 + g)*132 + c]);
                float2 u1  = *reinterpret_cast<const float2*>(&sA1[(m0 + 8 + g)*132 + c]);
                rmax[4*t+0] = fmaxf(rmax[4*t+0], (acc[t][0] + u0.x + a2v.x) * aj0);
                rmax[4*t+1] = fmaxf(rmax[4*t+1], (acc[t][1] + u0.y + a2v.y) * aj0);
                rmax[4*t+2] = fmaxf(rmax[4*t+2], (acc[t][2] + u1.x + a2v.x) * aj1);
                rmax[4*t+3] = fmaxf(rmax[4*t+3], (acc[t][3] + u1.y + a2v.y) * aj1);
            }
            if (cg == 0) {
                const int x = x0 + jx;
                const float q0 = cs[192 + 2*tig], q1 = cs[192 + 2*tig + 1];
                float2 o0, o1;
                o0.x = fmaxf(acct[0] + p1[0] + q0, 0.f);
                o0.y = fmaxf(acct[1] + p1[1] + q1, 0.f);
                o1.x = fmaxf(acct[2] + p1[2] + q0, 0.f);
                o1.y = fmaxf(acct[3] + p1[3] + q1, 0.f);
                float* tp = out_tri + (((size_t)b*NN + x)*NN + y0)*TT;
                *reinterpret_cast<float2*>(&tp[(m0 + g)*TT + 2*tig])     = o0;
                *reinterpret_cast<float2*>(&tp[(m0 + 8 + g)*TT + 2*tig]) = o1;
            }
        } else {
            // ---------- SIMT f32x2 path (cols 96..127) ----------
            unsigned long long acc[8];
            #pragma unroll
            for (int i = 0; i < 8; ++i) acc[i] = 0ull;
            const char* fb = smem + OFF_F + fs*FSLOT + (m0 + yq*4)*528;
            const char* wfb = smem + OFF_WF + dq*16;
            #pragma unroll 4
            for (int k0 = 0; k0 < 128; k0 += 4) {
                float4 a0 = *reinterpret_cast<const float4*>(fb + 0*528 + k0*4);
                float4 a1 = *reinterpret_cast<const float4*>(fb + 1*528 + k0*4);
                float4 a2 = *reinterpret_cast<const float4*>(fb + 2*528 + k0*4);
                float4 a3 = *reinterpret_cast<const float4*>(fb + 3*528 + k0*4);
                #define SIMT_STEP(kk, comp)                                          \
                {                                                                    \
                    ulonglong2 bp = *reinterpret_cast<const ulonglong2*>(            \
                        wfb + (k0 + kk)*128);                                        \
                    unsigned long long ap;                                           \
                    PACK2(ap, a0.comp); FFMA2(acc[0], ap, bp.x); FFMA2(acc[1], ap, bp.y); \
                    PACK2(ap, a1.comp); FFMA2(acc[2], ap, bp.x); FFMA2(acc[3], ap, bp.y); \
                    PACK2(ap, a2.comp); FFMA2(acc[4], ap, bp.x); FFMA2(acc[5], ap, bp.y); \
                    PACK2(ap, a3.comp); FFMA2(acc[6], ap, bp.x); FFMA2(acc[7], ap, bp.y); \
                }
                SIMT_STEP(0, x) SIMT_STEP(1, y) SIMT_STEP(2, z) SIMT_STEP(3, w)
                #undef SIMT_STEP
            }
            #pragma unroll
            for (int r = 0; r < 4; ++r) {
                const int y = m0 + yq*4 + r;
                const float aj = cs[128 + y];
                float4 u = *reinterpret_cast<const float4*>(&sA1[y*132 + dcol]);
                float4 a2v = *reinterpret_cast<const float4*>(&cs[dcol]);
                float e0, e1, e2, e3;
                UNPACK2(e0, e1, acc[r*2]);
                UNPACK2(e2, e3, acc[r*2 + 1]);
                rmax[r*4+0] = fmaxf(rmax[r*4+0], (e0 + u.x + a2v.x) * aj);
                rmax[r*4+1] = fmaxf(rmax[r*4+1], (e1 + u.y + a2v.y) * aj);
                rmax[r*4+2] = fmaxf(rmax[r*4+2], (e2 + u.z + a2v.z) * aj);
                rmax[r*4+3] = fmaxf(rmax[r*4+3], (e3 + u.w + a2v.w) * aj);
            }
        }

        // ---------- overlapped: convert tile jx+1, stage tile jx+2 ----------
        if (jx + 1 < TJ) {
            int nf = fs + 1; if (nf == 3) nf = 0;
            convert_tile(smem, tid, nf, (jx + 1) & 1);
        }
        if (jx + 2 < TJ) {
            int ns = fs + 2; if (ns >= 3) ns -= 3;
            stage_tile(sb, ns, tid, edge, adjp, b, x0 + jx + 2, y0);
        }
        CP_COMMIT();
        if (++fs == 3) fs = 0;
    }

    // ---- write partial maxes ----
    if (cg < 3) {
        const size_t base = (((size_t)(b*JC + xc))*NN + y0 + m0 + g)*DD;
        #pragma unroll
        for (int t = 0; t < 4; ++t) {
            const int c = cg*32 + t*8 + 2*tig;
            float2 v0 = { rmax[4*t+0], rmax[4*t+1] };
            float2 v1 = { rmax[4*t+2], rmax[4*t+3] };
            *reinterpret_cast<float2*>(&d_pmax[base + c])        = v0;
            *reinterpret_cast<float2*>(&d_pmax[base + 8*DD + c]) = v1;
        }
    } else {
        const size_t base = (((size_t)(b*JC + xc))*NN + y0 + m0 + yq*4)*DD + dcol;
        #pragma unroll
        for (int r = 0; r < 4; ++r) {
            float4 v = { rmax[r*4+0], rmax[r*4+1], rmax[r*4+2], rmax[r*4+3] };
            *reinterpret_cast<float4*>(&d_pmax[base + (size_t)r*DD]) = v;
        }
    }
}

// ---------------- final reduce + output linear -------------------------------
__global__ __launch_bounds__(128) void k_reduce(
    const float* __restrict__ Wo2, const float* __restrict__ bo2,
    float* __restrict__ out_ret)
{
    __shared__ float sM[4][128];
    const int tid = threadIdx.x;
    const int gr0 = blockIdx.x * 4;
    const int b = gr0 >> 9;
    {
        const int r = tid >> 5, q = tid & 31;
        const int y = (gr0 + r) & 511;
        float4 m = { __int_as_float(0xff800000), __int_as_float(0xff800000),
                     __int_as_float(0xff800000), __int_as_float(0xff800000) };
        #pragma unroll
        for (int xc = 0; xc < JC; ++xc) {
            float4 v = *reinterpret_cast<const float4*>(
                &d_pmax[(((size_t)(b*JC + xc))*NN + y)*DD + q*4]);
            m.x = fmaxf(m.x, v.x); m.y = fmaxf(m.y, v.y);
            m.z = fmaxf(m.z, v.z); m.w = fmaxf(m.w, v.w);
        }
        *reinterpret_cast<float4*>(&sM[r][q*4]) = m;
    }
    __syncthreads();
    #pragma unroll
    for (int i = 0; i < 4; ++i) {
        int idx = tid + i*128;
        int r = idx >> 7, d = idx & 127;
        int gid = gr0 + r;
        float s = 0.f;
        #pragma unroll 8
        for (int k = 0; k < 128; ++k) s = fmaf(sM[r][k], Wo2[k*DD + d], s);
        out_ret[(size_t)gid*DD + d] = d_O1[(size_t)gid*DD + d] + s + bo2[d];
    }
}

// ---------------- launch ------------------------------------------------------
extern "C" void kernel_launch(void* const* d_in, const int* in_sizes, int n_in,
                              void* d_out, int out_size)
{
    const float* node   = (const float*)d_in[0];
    const float* edge   = (const float*)d_in[1];
    const float* graph  = (const float*)d_in[2];
    const float* adj    = (const float*)d_in[3];
    const float* hidden = (const float*)d_in[4];
    const float* Wm1 = (const float*)d_in[5],  *bm1 = (const float*)d_in[6];
    const float* Wm2 = (const float*)d_in[7],  *bm2 = (const float*)d_in[8];
    const float* Wme = (const float*)d_in[9],  *bme = (const float*)d_in[10];
    const float* Wmg = (const float*)d_in[11], *bmg = (const float*)d_in[12];
    const float* Wo1 = (const float*)d_in[13], *bo1 = (const float*)d_in[14];
    const float* Wo2 = (const float*)d_in[15], *bo2 = (const float*)d_in[16];
    const float* Wt1 = (const float*)d_in[17], *bt1 = (const float*)d_in[18];
    const float* Wt2 = (const float*)d_in[19], *bt2 = (const float*)d_in[20];
    const float* Wte = (const float*)d_in[21], *bte = (const float*)d_in[22];
    const float* Wtg = (const float*)d_in[23], *btg = (const float*)d_in[24];

    float* out_ret = (float*)d_out;                   // [2,512,128]
    float* out_tri = out_ret + (size_t)BB*NN*DD;      // [2,512,512,8]

    k_node<<<BB*NN/8, 256>>>(node, hidden, graph, Wm1, bm1, Wm2, bm2,
                             Wo1, bo1, Wt1, bt1, Wt2, bt2,
                             bme, Wmg, bmg, Wtg, bte, btg);
    k_dummy<<<1, 32>>>();
    k_dummy<<<1, 32>>>();
    cudaFuncSetAttribute(k_edge, cudaFuncAttributeMaxDynamicSharedMemorySize, SMEM_EDGE);
    k_edge<<<dim3(JC, NN/TY, BB), 512, SMEM_EDGE>>>(edge, adj, Wme, Wte, out_tri);
    k_reduce<<<BB*NN/4, 128>>>(Wo2, bo2, out_ret);
}

// round 9
// speedup vs baseline: 1.7118x; 1.7118x over previous
#include <cuda_runtime.h>
#include <cuda_fp16.h>
#include <stdint.h>

#define BB 2
#define NN 512
#define HH 128
#define DD 128
#define TT 8
#define ZK 256
#define JC 8      // sender (x) chunks
#define TJ 64     // senders per chunk
#define TY 32     // receivers (y) per CTA tile

// ---------------- device scratch ------------------------------------------
__device__ float d_A1[BB*NN*DD];    // z@Wm1 + bm1 + bme + (g@Wmg + bmg)
__device__ float d_A2[BB*NN*DD];    // z@Wm2 + bm2
__device__ float d_O1[BB*NN*DD];    // z@Wo1 + bo1
__device__ float d_P1[BB*NN*TT];    // z@Wt1 + bt1 + bte + (g@Wtg + btg)
__device__ float d_P2[BB*NN*TT];    // z@Wt2 + bt2
__device__ float d_pmax[BB*JC*NN*DD];   // partial masked maxes, 4 MB

// ---------------- helpers ----------------------------------------------------
__device__ __forceinline__ uint32_t smem_u32(const void* p) {
    uint32_t a;
    asm("{ .reg .u64 t; cvta.to.shared.u64 t, %1; cvt.u32.u64 %0, t; }"
        : "=r"(a) : "l"(p));
    return a;
}
__device__ __forceinline__ void cp16(uint32_t s, const void* g) {
    asm volatile("cp.async.cg.shared.global [%0], [%1], 16;"
                 :: "r"(s), "l"(__cvta_generic_to_global(g)));
}
#define CP_COMMIT() asm volatile("cp.async.commit_group;" ::: "memory")
#define CP_WAIT(N)  asm volatile("cp.async.wait_group %0;" :: "n"(N) : "memory")

#define MMA4(acc, a0, a1, a2, a3, b0, b1)                                   \
    asm volatile("mma.sync.aligned.m16n8k16.row.col.f32.f16.f16.f32 "       \
                 "{%0,%1,%2,%3}, {%4,%5,%6,%7}, {%8,%9}, {%0,%1,%2,%3};"    \
                 : "+f"((acc)[0]), "+f"((acc)[1]), "+f"((acc)[2]), "+f"((acc)[3]) \
                 : "r"(a0), "r"(a1), "r"(a2), "r"(a3), "r"(b0), "r"(b1))

// ---------------- per-node linears (graph projections folded in) -------------
__global__ __launch_bounds__(256) void k_node(
    const float* __restrict__ node, const float* __restrict__ hidden,
    const float* __restrict__ gf,
    const float* __restrict__ Wm1, const float* __restrict__ bm1,
    const float* __restrict__ Wm2, const float* __restrict__ bm2,
    const float* __restrict__ Wo1, const float* __restrict__ bo1,
    const float* __restrict__ Wt1, const float* __restrict__ bt1,
    const float* __restrict__ Wt2, const float* __restrict__ bt2,
    const float* __restrict__ Wme_b, const float* __restrict__ Wmg,
    const float* __restrict__ bmg,
    const float* __restrict__ Wtg, const float* __restrict__ bte,
    const float* __restrict__ btg)
{
    __shared__ float zt[8][ZK];
    __shared__ float gG[128];
    __shared__ float gGt[8];
    const int tid = threadIdx.x;
    const int g0 = blockIdx.x * 8;
    const int b = g0 >> 9;                 // all 8 rows share one batch
    for (int idx = tid; idx < 8*ZK; idx += 256) {
        int r = idx >> 8, c = idx & 255;
        size_t gid = (size_t)(g0 + r);
        zt[r][c] = (c < HH) ? node[gid*HH + c] : hidden[gid*HH + (c - HH)];
    }
    if (tid < 128) {                       // graph proj (msg): g@Wmg + bme + bmg
        float s = 0.f;
        #pragma unroll 4
        for (int h = 0; h < HH; ++h) s = fmaf(gf[b*HH + h], Wmg[h*DD + tid], s);
        gG[tid] = s + Wme_b[tid] + bmg[tid];
    } else if (tid < 136) {                // graph proj (tri): g@Wtg + bte + btg
        int tt = tid - 128;
        float s = 0.f;
        #pragma unroll 4
        for (int h = 0; h < HH; ++h) s = fmaf(gf[b*HH + h], Wtg[h*TT + tt], s);
        gGt[tt] = s + bte[tt] + btg[tt];
    }
    __syncthreads();
    const int d = tid & 127, nh = tid >> 7;
    float s1[4] = {0,0,0,0}, s2[4] = {0,0,0,0}, so[4] = {0,0,0,0};
    #pragma unroll 4
    for (int k = 0; k < ZK; ++k) {
        float w1 = Wm1[k*DD + d], w2 = Wm2[k*DD + d], wo = Wo1[k*DD + d];
        #pragma unroll
        for (int r = 0; r < 4; ++r) {
            float z = zt[nh*4 + r][k];
            s1[r] = fmaf(z, w1, s1[r]);
            s2[r] = fmaf(z, w2, s2[r]);
            so[r] = fmaf(z, wo, so[r]);
        }
    }
    #pragma unroll
    for (int r = 0; r < 4; ++r) {
        int gid = g0 + nh*4 + r;
        d_A1[(size_t)gid*DD + d] = s1[r] + bm1[d] + gG[d];
        d_A2[(size_t)gid*DD + d] = s2[r] + bm2[d];
        d_O1[(size_t)gid*DD + d] = so[r] + bo1[d];
    }
    if (tid < 128) {
        int r = tid >> 4, tt = (tid >> 1) & 7, which = tid & 1;
        const float* W = which ? Wt2 : Wt1;
        float s = 0.f;
        #pragma unroll 4
        for (int k = 0; k < ZK; ++k) s = fmaf(zt[r][k], W[k*TT + tt], s);
        int gid = g0 + r;
        if (which) d_P2[gid*TT + tt] = s + bt2[tt];
        else       d_P1[gid*TT + tt] = s + bt1[tt] + gGt[tt];
    }
}

// ---------------- dummy (profiling slot alignment) ---------------------------
__global__ void k_dummy() {}

// ---------------- fused edge pass --------------------------------------------
// 256 threads, 8 warps: warp = (m-tile 0..1) x (col-group 0..3); cg0 also tri.
// smem layout (bytes)
#define HB      8704                        // fp16 tile buf: 32 rows * 272 B
#define OFF_SA  0                           // 3 bufs              26112
#define OFF_WTRI 26112                      // fp16 Wte [8][136]    2176 -> pad 2304
#define OFF_C   28416                       // 3 const slots x 1024 3072
#define OFF_SA1 31488                       // fp32 A1 [32][132]   16896
#define SMEM_EDGE 48384

__device__ __forceinline__ void stage_consts(
    uint32_t sb, int slot, int tid,
    const float* __restrict__ adjp, int b, int x, int y0)
{
    if (tid < 42) {
        uint32_t cb = sb + OFF_C + (uint32_t)slot * 1024u;
        const float* src;
        uint32_t off;
        if (tid < 32)      { src = d_A2 + ((size_t)b*NN + x)*DD + tid*4;           off = tid*16u; }
        else if (tid < 40) { src = adjp + ((size_t)b*NN + x)*NN + y0 + (tid-32)*4; off = 512u + (tid-32)*16u; }
        else               { src = d_P2 + ((size_t)b*NN + x)*TT + (tid-40)*4;      off = 640u + (tid-40)*16u; }
        cp16(cb + off, src);
    }
}

__global__ __launch_bounds__(256, 2) void k_edge(
    const float* __restrict__ edge, const float* __restrict__ adjp,
    const float* __restrict__ Wme, const float* __restrict__ Wte,
    float* __restrict__ out_tri)
{
    extern __shared__ char smem[];
    const uint32_t sb = smem_u32(smem);
    float* sA1    = reinterpret_cast<float*>(smem + OFF_SA1);
    __half* sWtri = reinterpret_cast<__half*>(smem + OFF_WTRI);

    const int tid = threadIdx.x;
    const int w = tid >> 5, lane = tid & 31;
    const int m0 = (w & 1) * 16;          // m-tile base row (0 or 16)
    const int cg = w >> 1;                // col group 0..3 (cols cg*32..+31); cg0 also tri
    const int g = lane >> 2, tig = lane & 3;
    const int xc = blockIdx.x, yt = blockIdx.y, b = blockIdx.z;
    const int y0 = yt * TY;
    const int x0 = xc * TJ;

    // ---- one-time: A1 -> smem (stride 132) ----
    {
        const float4* a1src = reinterpret_cast<const float4*>(d_A1 + ((size_t)b*NN + y0)*DD);
        #pragma unroll
        for (int i = 0; i < 4; ++i) {
            int idx = tid + i*256;                       // float4 index 0..1023
            float4 v = a1src[idx];
            *reinterpret_cast<float4*>(&sA1[(idx >> 5)*132 + (idx & 31)*4]) = v;
        }
    }
    // ---- one-time: tri weights fp16 [t][k], stride 136 halves (bank-safe) ----
    #pragma unroll
    for (int i = 0; i < 2; ++i) {
        int idx = tid + i*256;                           // half2 index 0..511
        int t = idx >> 6, k = (idx & 63) * 2;
        __half2 h = __floats2half2_rn(Wte[k*TT + t], Wte[(k+1)*TT + t]);
        *reinterpret_cast<__half2*>(&sWtri[t*136 + k]) = h;
    }
    // ---- one-time: B fragments (cols cg*32..+31) -> registers ----
    uint32_t Br[8][4][2];
    {
        const int nb = cg*32 + g;
        #pragma unroll
        for (int ks = 0; ks < 8; ++ks) {
            const int k0 = ks*16 + 2*tig;
            #pragma unroll
            for (int t = 0; t < 4; ++t) {
                const int n = nb + t*8;
                __half2 lo = __floats2half2_rn(Wme[k0*DD + n],     Wme[(k0+1)*DD + n]);
                __half2 hi = __floats2half2_rn(Wme[(k0+8)*DD + n], Wme[(k0+9)*DD + n]);
                Br[ks][t][0] = *reinterpret_cast<uint32_t*>(&lo);
                Br[ks][t][1] = *reinterpret_cast<uint32_t*>(&hi);
            }
        }
    }
    // ---- one-time: P1 regs (tri handled by cg==0 warps) ----
    float p1[4] = {0,0,0,0};
    if (cg == 0) {
        const size_t r0 = ((size_t)b*NN + y0 + m0 + g)*TT;
        p1[0] = d_P1[r0 + 2*tig];           p1[1] = d_P1[r0 + 2*tig + 1];
        p1[2] = d_P1[r0 + 8*TT + 2*tig];    p1[3] = d_P1[r0 + 8*TT + 2*tig + 1];
    }

    float rmax[16];
    #pragma unroll
    for (int i = 0; i < 16; ++i) rmax[i] = __int_as_float(0xff800000);

    const uint32_t ldmb0 = sb + OFF_SA
        + (uint32_t)(m0 + ((lane >> 3) & 1)*8 + (lane & 7)) * 272u
        + (uint32_t)((lane >> 4) & 1) * 16u;

    // per-thread tile staging geometry: row = tid>>3, 16 floats at col (tid&7)*16
    const int srow = tid >> 3, scol = (tid & 7) * 16;
    const uint32_t sts_dst = sb + OFF_SA /*+slot*HB*/ + (uint32_t)srow*272u + (uint32_t)(tid & 7)*32u;

    // ---- prologue: consts 0,1 (cp.async), tile 0 (LDG->cvt->STS buf0) ----
    stage_consts(sb, 0, tid, adjp, b, x0,     y0); CP_COMMIT();
    stage_consts(sb, 1, tid, adjp, b, x0 + 1, y0); CP_COMMIT();
    {
        const float4* ep = reinterpret_cast<const float4*>(
            edge + (((size_t)b*NN + x0)*NN + y0 + srow)*DD + scol);
        float4 f0 = ep[0], f1 = ep[1], f2 = ep[2], f3 = ep[3];
        __half2 h0 = __floats2half2_rn(f0.x, f0.y), h1 = __floats2half2_rn(f0.z, f0.w);
        __half2 h2 = __floats2half2_rn(f1.x, f1.y), h3 = __floats2half2_rn(f1.z, f1.w);
        __half2 h4 = __floats2half2_rn(f2.x, f2.y), h5 = __floats2half2_rn(f2.z, f2.w);
        __half2 h6 = __floats2half2_rn(f3.x, f3.y), h7 = __floats2half2_rn(f3.z, f3.w);
        uint4 o0, o1;
        o0.x = *reinterpret_cast<uint32_t*>(&h0); o0.y = *reinterpret_cast<uint32_t*>(&h1);
        o0.z = *reinterpret_cast<uint32_t*>(&h2); o0.w = *reinterpret_cast<uint32_t*>(&h3);
        o1.x = *reinterpret_cast<uint32_t*>(&h4); o1.y = *reinterpret_cast<uint32_t*>(&h5);
        o1.z = *reinterpret_cast<uint32_t*>(&h6); o1.w = *reinterpret_cast<uint32_t*>(&h7);
        *reinterpret_cast<uint4*>(smem + (sts_dst - sb))      = o0;
        *reinterpret_cast<uint4*>(smem + (sts_dst - sb) + 16) = o1;
    }

    int slot = 0;                          // fp16/const slot of current tile = jx % 3
    for (int jx = 0; jx < TJ; ++jx) {
        CP_WAIT(1);                        // consts jx complete
        __syncthreads();                   // tile jx STS + consts visible

        // -- prefetch tile jx+1 into registers (LDG latency covered by MMAs) --
        float4 f0, f1, f2, f3;
        const bool havepf = (jx + 1 < TJ);
        if (havepf) {
            const float4* ep = reinterpret_cast<const float4*>(
                edge + (((size_t)b*NN + x0 + jx + 1)*NN + y0 + srow)*DD + scol);
            f0 = ep[0]; f1 = ep[1]; f2 = ep[2]; f3 = ep[3];
        }
        // -- consts jx+2 --
        if (jx + 2 < TJ) {
            int ns = slot + 2; if (ns >= 3) ns -= 3;
            stage_consts(sb, ns, tid, adjp, b, x0 + jx + 2, y0);
        }
        CP_COMMIT();

        const float* cs = reinterpret_cast<const float*>(smem + OFF_C) + slot*256;

        // ---------- MMA ----------
        float acc[4][4] = {{0,0,0,0},{0,0,0,0},{0,0,0,0},{0,0,0,0}};
        float acct[4] = {0,0,0,0};
        const uint32_t ldmb = ldmb0 + (uint32_t)slot*(uint32_t)HB;
        #pragma unroll
        for (int ks = 0; ks < 8; ++ks) {
            uint32_t a0, a1, a2, a3;
            asm volatile("ldmatrix.sync.aligned.m8n8.x4.shared.b16 {%0,%1,%2,%3}, [%4];"
                         : "=r"(a0), "=r"(a1), "=r"(a2), "=r"(a3)
                         : "r"(ldmb + (uint32_t)ks*32u));
            #pragma unroll
            for (int t = 0; t < 4; ++t)
                MMA4(acc[t], a0, a1, a2, a3, Br[ks][t][0], Br[ks][t][1]);
            if (cg == 0) {
                uint32_t b0 = *reinterpret_cast<const uint32_t*>(&sWtri[g*136 + ks*16 + 2*tig]);
                uint32_t b1 = *reinterpret_cast<const uint32_t*>(&sWtri[g*136 + ks*16 + 2*tig + 8]);
                MMA4(acct, a0, a1, a2, a3, b0, b1);
            }
        }

        // ---------- fused epilogue ----------
        const float aj0 = cs[128 + m0 + g];
        const float aj1 = cs[128 + m0 + 8 + g];
        #pragma unroll
        for (int t = 0; t < 4; ++t) {
            const int c = cg*32 + t*8 + 2*tig;
            float2 a2v = *reinterpret_cast<const float2*>(&cs[c]);
            float2 u0  = *reinterpret_cast<const float2*>(&sA1[(m0 + g)*132 + c]);
            float2 u1  = *reinterpret_cast<const float2*>(&sA1[(m0 + 8 + g)*132 + c]);
            rmax[4*t+0] = fmaxf(rmax[4*t+0], (acc[t][0] + u0.x + a2v.x) * aj0);
            rmax[4*t+1] = fmaxf(rmax[4*t+1], (acc[t][1] + u0.y + a2v.y) * aj0);
            rmax[4*t+2] = fmaxf(rmax[4*t+2], (acc[t][2] + u1.x + a2v.x) * aj1);
            rmax[4*t+3] = fmaxf(rmax[4*t+3], (acc[t][3] + u1.y + a2v.y) * aj1);
        }
        if (cg == 0) {
            const int x = x0 + jx;
            const float q0 = cs[160 + 2*tig], q1 = cs[160 + 2*tig + 1];
            float2 o0, o1;
            o0.x = fmaxf(acct[0] + p1[0] + q0, 0.f);
            o0.y = fmaxf(acct[1] + p1[1] + q1, 0.f);
            o1.x = fmaxf(acct[2] + p1[2] + q0, 0.f);
            o1.y = fmaxf(acct[3] + p1[3] + q1, 0.f);
            float* tp = out_tri + (((size_t)b*NN + x)*NN + y0)*TT;
            *reinterpret_cast<float2*>(&tp[(m0 + g)*TT + 2*tig])     = o0;
            *reinterpret_cast<float2*>(&tp[(m0 + 8 + g)*TT + 2*tig]) = o1;
        }

        // ---------- convert prefetched tile -> fp16 buf (jx+1)%3 ----------
        if (havepf) {
            int ns = slot + 1; if (ns == 3) ns = 0;
            __half2 h0 = __floats2half2_rn(f0.x, f0.y), h1 = __floats2half2_rn(f0.z, f0.w);
            __half2 h2 = __floats2half2_rn(f1.x, f1.y), h3 = __floats2half2_rn(f1.z, f1.w);
            __half2 h4 = __floats2half2_rn(f2.x, f2.y), h5 = __floats2half2_rn(f2.z, f2.w);
            __half2 h6 = __floats2half2_rn(f3.x, f3.y), h7 = __floats2half2_rn(f3.z, f3.w);
            uint4 o0, o1;
            o0.x = *reinterpret_cast<uint32_t*>(&h0); o0.y = *reinterpret_cast<uint32_t*>(&h1);
            o0.z = *reinterpret_cast<uint32_t*>(&h2); o0.w = *reinterpret_cast<uint32_t*>(&h3);
            o1.x = *reinterpret_cast<uint32_t*>(&h4); o1.y = *reinterpret_cast<uint32_t*>(&h5);
            o1.z = *reinterpret_cast<uint32_t*>(&h6); o1.w = *reinterpret_cast<uint32_t*>(&h7);
            char* dst = smem + (sts_dst - sb) + ns*HB;
            *reinterpret_cast<uint4*>(dst)      = o0;
            *reinterpret_cast<uint4*>(dst + 16) = o1;
        }
        if (++slot == 3) slot = 0;
    }

    // ---- write partial maxes for this x-chunk ----
    {
        const size_t base = (((size_t)(b*JC + xc))*NN + y0 + m0 + g)*DD;
        #pragma unroll
        for (int t = 0; t < 4; ++t) {
            const int c = cg*32 + t*8 + 2*tig;
            float2 v0 = { rmax[4*t+0], rmax[4*t+1] };
            float2 v1 = { rmax[4*t+2], rmax[4*t+3] };
            *reinterpret_cast<float2*>(&d_pmax[base + c])        = v0;
            *reinterpret_cast<float2*>(&d_pmax[base + 8*DD + c]) = v1;
        }
    }
}

// ---------------- final reduce + output linear -------------------------------
__global__ __launch_bounds__(128) void k_reduce(
    const float* __restrict__ Wo2, const float* __restrict__ bo2,
    float* __restrict__ out_ret)
{
    __shared__ float sM[4][128];
    const int tid = threadIdx.x;
    const int gr0 = blockIdx.x * 4;
    const int b = gr0 >> 9;
    {
        const int r = tid >> 5, q = tid & 31;
        const int y = (gr0 + r) & 511;
        float4 m = { __int_as_float(0xff800000), __int_as_float(0xff800000),
                     __int_as_float(0xff800000), __int_as_float(0xff800000) };
        #pragma unroll
        for (int xc = 0; xc < JC; ++xc) {
            float4 v = *reinterpret_cast<const float4*>(
                &d_pmax[(((size_t)(b*JC + xc))*NN + y)*DD + q*4]);
            m.x = fmaxf(m.x, v.x); m.y = fmaxf(m.y, v.y);
            m.z = fmaxf(m.z, v.z); m.w = fmaxf(m.w, v.w);
        }
        *reinterpret_cast<float4*>(&sM[r][q*4]) = m;
    }
    __syncthreads();
    #pragma unroll
    for (int i = 0; i < 4; ++i) {
        int idx = tid + i*128;
        int r = idx >> 7, d = idx & 127;
        int gid = gr0 + r;
        float s = 0.f;
        #pragma unroll 8
        for (int k = 0; k < 128; ++k) s = fmaf(sM[r][k], Wo2[k*DD + d], s);
        out_ret[(size_t)gid*DD + d] = d_O1[(size_t)gid*DD + d] + s + bo2[d];
    }
}

// ---------------- launch ------------------------------------------------------
extern "C" void kernel_launch(void* const* d_in, const int* in_sizes, int n_in,
                              void* d_out, int out_size)
{
    const float* node   = (const float*)d_in[0];
    const float* edge   = (const float*)d_in[1];
    const float* graph  = (const float*)d_in[2];
    const float* adj    = (const float*)d_in[3];
    const float* hidden = (const float*)d_in[4];
    const float* Wm1 = (const float*)d_in[5],  *bm1 = (const float*)d_in[6];
    const float* Wm2 = (const float*)d_in[7],  *bm2 = (const float*)d_in[8];
    const float* Wme = (const float*)d_in[9],  *bme = (const float*)d_in[10];
    const float* Wmg = (const float*)d_in[11], *bmg = (const float*)d_in[12];
    const float* Wo1 = (const float*)d_in[13], *bo1 = (const float*)d_in[14];
    const float* Wo2 = (const float*)d_in[15], *bo2 = (const float*)d_in[16];
    const float* Wt1 = (const float*)d_in[17], *bt1 = (const float*)d_in[18];
    const float* Wt2 = (const float*)d_in[19], *bt2 = (const float*)d_in[20];
    const float* Wte = (const float*)d_in[21], *bte = (const float*)d_in[22];
    const float* Wtg = (const float*)d_in[23], *btg = (const float*)d_in[24];

    float* out_ret = (float*)d_out;                   // [2,512,128]
    float* out_tri = out_ret + (size_t)BB*NN*DD;      // [2,512,512,8]

    k_node<<<BB*NN/8, 256>>>(node, hidden, graph, Wm1, bm1, Wm2, bm2,
                             Wo1, bo1, Wt1, bt1, Wt2, bt2,
                             bme, Wmg, bmg, Wtg, bte, btg);
    k_dummy<<<1, 32>>>();
    k_dummy<<<1, 32>>>();
    cudaFuncSetAttribute(k_edge, cudaFuncAttributeMaxDynamicSharedMemorySize, SMEM_EDGE);
    k_edge<<<dim3(JC, NN/TY, BB), 256, SMEM_EDGE>>>(edge, adj, Wme, Wte, out_tri);
    k_reduce<<<BB*NN/4, 128>>>(Wo2, bo2, out_ret);
}

// round 10
// speedup vs baseline: 2.4450x; 1.4283x over previous
#include <cuda_runtime.h>
#include <cuda_fp16.h>
#include <stdint.h>

#define BB 2
#define NN 512
#define HH 128
#define DD 128
#define TT 8
#define ZK 256
#define JC 8      // sender (x) chunks
#define TJ 64     // senders per chunk
#define TY 32     // receivers (y) per CTA tile

// ---------------- device scratch ------------------------------------------
__device__ float d_A1[BB*NN*DD];    // z@Wm1 + bm1 + bme + (g@Wmg + bmg)
__device__ float d_A2[BB*NN*DD];    // z@Wm2 + bm2
__device__ float d_O1[BB*NN*DD];    // z@Wo1 + bo1
__device__ float d_P1[BB*NN*TT];    // z@Wt1 + bt1 + bte + (g@Wtg + btg)
__device__ float d_P2[BB*NN*TT];    // z@Wt2 + bt2
__device__ float d_pmax[BB*JC*NN*DD];   // partial masked maxes, 4 MB

// ---------------- helpers ----------------------------------------------------
__device__ __forceinline__ uint32_t smem_u32(const void* p) {
    uint32_t a;
    asm("{ .reg .u64 t; cvta.to.shared.u64 t, %1; cvt.u32.u64 %0, t; }"
        : "=r"(a) : "l"(p));
    return a;
}
__device__ __forceinline__ void cp16(uint32_t s, const void* g) {
    asm volatile("cp.async.cg.shared.global [%0], [%1], 16;"
                 :: "r"(s), "l"(__cvta_generic_to_global(g)));
}
#define CP_COMMIT() asm volatile("cp.async.commit_group;" ::: "memory")
#define CP_WAIT(N)  asm volatile("cp.async.wait_group %0;" :: "n"(N) : "memory")

#define MMA4(acc, a0, a1, a2, a3, b0, b1)                                   \
    asm volatile("mma.sync.aligned.m16n8k16.row.col.f32.f16.f16.f32 "       \
                 "{%0,%1,%2,%3}, {%4,%5,%6,%7}, {%8,%9}, {%0,%1,%2,%3};"    \
                 : "+f"((acc)[0]), "+f"((acc)[1]), "+f"((acc)[2]), "+f"((acc)[3]) \
                 : "r"(a0), "r"(a1), "r"(a2), "r"(a3), "r"(b0), "r"(b1))

// ---------------- per-node linears (graph projections folded in) -------------
__global__ __launch_bounds__(256) void k_node(
    const float* __restrict__ node, const float* __restrict__ hidden,
    const float* __restrict__ gf,
    const float* __restrict__ Wm1, const float* __restrict__ bm1,
    const float* __restrict__ Wm2, const float* __restrict__ bm2,
    const float* __restrict__ Wo1, const float* __restrict__ bo1,
    const float* __restrict__ Wt1, const float* __restrict__ bt1,
    const float* __restrict__ Wt2, const float* __restrict__ bt2,
    const float* __restrict__ Wme_b, const float* __restrict__ Wmg,
    const float* __restrict__ bmg,
    const float* __restrict__ Wtg, const float* __restrict__ bte,
    const float* __restrict__ btg)
{
    __shared__ float zt[4][ZK];
    __shared__ float gG[128];
    __shared__ float gGt[8];
    const int tid = threadIdx.x;
    const int g0 = blockIdx.x * 4;
    const int b = g0 >> 9;
    for (int idx = tid; idx < 4*ZK; idx += 256) {
        int r = idx >> 8, c = idx & 255;
        size_t gid = (size_t)(g0 + r);
        zt[r][c] = (c < HH) ? node[gid*HH + c] : hidden[gid*HH + (c - HH)];
    }
    if (tid < 128) {                       // graph proj (msg): g@Wmg + bme + bmg
        float s = 0.f;
        #pragma unroll 4
        for (int h = 0; h < HH; ++h) s = fmaf(gf[b*HH + h], Wmg[h*DD + tid], s);
        gG[tid] = s + Wme_b[tid] + bmg[tid];
    } else if (tid < 136) {                // graph proj (tri): g@Wtg + bte + btg
        int tt = tid - 128;
        float s = 0.f;
        #pragma unroll 4
        for (int h = 0; h < HH; ++h) s = fmaf(gf[b*HH + h], Wtg[h*TT + tt], s);
        gGt[tt] = s + bte[tt] + btg[tt];
    }
    __syncthreads();
    const int d = tid & 127, nh = tid >> 7;
    float s1[2] = {0,0}, s2[2] = {0,0}, so[2] = {0,0};
    #pragma unroll 4
    for (int k = 0; k < ZK; ++k) {
        float w1 = Wm1[k*DD + d], w2 = Wm2[k*DD + d], wo = Wo1[k*DD + d];
        #pragma unroll
        for (int r = 0; r < 2; ++r) {
            float z = zt[nh*2 + r][k];
            s1[r] = fmaf(z, w1, s1[r]);
            s2[r] = fmaf(z, w2, s2[r]);
            so[r] = fmaf(z, wo, so[r]);
        }
    }
    #pragma unroll
    for (int r = 0; r < 2; ++r) {
        int gid = g0 + nh*2 + r;
        d_A1[(size_t)gid*DD + d] = s1[r] + bm1[d] + gG[d];
        d_A2[(size_t)gid*DD + d] = s2[r] + bm2[d];
        d_O1[(size_t)gid*DD + d] = so[r] + bo1[d];
    }
    if (tid < 64) {
        int r = tid >> 4, tt = (tid >> 1) & 7, which = tid & 1;
        const float* W = which ? Wt2 : Wt1;
        float s = 0.f;
        #pragma unroll 4
        for (int k = 0; k < ZK; ++k) s = fmaf(zt[r][k], W[k*TT + tt], s);
        int gid = g0 + r;
        if (which) d_P2[gid*TT + tt] = s + bt2[tt];
        else       d_P1[gid*TT + tt] = s + bt1[tt] + gGt[tt];
    }
}

// ---------------- dummy (profiling slot alignment) ---------------------------
__global__ void k_dummy() {}

// ---------------- fused edge pass --------------------------------------------
// 256 threads, 8 warps: warp = (m-tile 0..1) x (col-group 0..3); cg0 also tri.
// smem layout (bytes)
#define HB      8704                        // fp16 tile buf: 32 rows * 272 B
#define OFF_SA  0                           // 4 bufs              34816
#define OFF_WTRI 34816                      // fp16 Wte [8][136]    2176 -> pad 2304
#define OFF_C   37120                       // 8 const slots x 1024 8192
#define OFF_SA1 45312                       // fp32 A1 [32][132]   16896
#define SMEM_EDGE 62208

__device__ __forceinline__ void stage_consts(
    uint32_t sb, int x, int tid,
    const float* __restrict__ adjp, int b, int y0)
{
    if (tid < 42) {
        uint32_t cb = sb + OFF_C + (uint32_t)(x & 7) * 1024u;
        const float* src;
        uint32_t off;
        if (tid < 32)      { src = d_A2 + ((size_t)b*NN + x)*DD + tid*4;           off = tid*16u; }
        else if (tid < 40) { src = adjp + ((size_t)b*NN + x)*NN + y0 + (tid-32)*4; off = 512u + (tid-32)*16u; }
        else               { src = d_P2 + ((size_t)b*NN + x)*TT + (tid-40)*4;      off = 640u + (tid-40)*16u; }
        cp16(cb + off, src);
    }
}

__global__ __launch_bounds__(256, 2) void k_edge(
    const float* __restrict__ edge, const float* __restrict__ adjp,
    const float* __restrict__ Wme, const float* __restrict__ Wte,
    float* __restrict__ out_tri)
{
    extern __shared__ char smem[];
    const uint32_t sb = smem_u32(smem);
    float* sA1    = reinterpret_cast<float*>(smem + OFF_SA1);
    __half* sWtri = reinterpret_cast<__half*>(smem + OFF_WTRI);

    const int tid = threadIdx.x;
    const int w = tid >> 5, lane = tid & 31;
    const int m0 = (w & 1) * 16;          // m-tile base row (0 or 16)
    const int cg = w >> 1;                // col group 0..3 (cols cg*32..+31); cg0 also tri
    const int g = lane >> 2, tig = lane & 3;
    const int xc = blockIdx.x, yt = blockIdx.y, b = blockIdx.z;
    const int y0 = yt * TY;
    const int x0 = xc * TJ;

    // ---- one-time: A1 -> smem (stride 132) ----
    {
        const float4* a1src = reinterpret_cast<const float4*>(d_A1 + ((size_t)b*NN + y0)*DD);
        #pragma unroll
        for (int i = 0; i < 4; ++i) {
            int idx = tid + i*256;                       // float4 index 0..1023
            float4 v = a1src[idx];
            *reinterpret_cast<float4*>(&sA1[(idx >> 5)*132 + (idx & 31)*4]) = v;
        }
    }
    // ---- one-time: tri weights fp16 [t][k], stride 136 halves ----
    #pragma unroll
    for (int i = 0; i < 2; ++i) {
        int idx = tid + i*256;                           // half2 index 0..511
        int t = idx >> 6, k = (idx & 63) * 2;
        __half2 h = __floats2half2_rn(Wte[k*TT + t], Wte[(k+1)*TT + t]);
        *reinterpret_cast<__half2*>(&sWtri[t*136 + k]) = h;
    }
    // ---- one-time: B fragments (cols cg*32..+31) -> registers ----
    uint32_t Br[8][4][2];
    {
        const int nb = cg*32 + g;
        #pragma unroll
        for (int ks = 0; ks < 8; ++ks) {
            const int k0 = ks*16 + 2*tig;
            #pragma unroll
            for (int t = 0; t < 4; ++t) {
                const int n = nb + t*8;
                __half2 lo = __floats2half2_rn(Wme[k0*DD + n],     Wme[(k0+1)*DD + n]);
                __half2 hi = __floats2half2_rn(Wme[(k0+8)*DD + n], Wme[(k0+9)*DD + n]);
                Br[ks][t][0] = *reinterpret_cast<uint32_t*>(&lo);
                Br[ks][t][1] = *reinterpret_cast<uint32_t*>(&hi);
            }
        }
    }
    // ---- one-time: P1 regs (tri handled by cg==0 warps) ----
    float p1[4] = {0,0,0,0};
    if (cg == 0) {
        const size_t r0 = ((size_t)b*NN + y0 + m0 + g)*TT;
        p1[0] = d_P1[r0 + 2*tig];           p1[1] = d_P1[r0 + 2*tig + 1];
        p1[2] = d_P1[r0 + 8*TT + 2*tig];    p1[3] = d_P1[r0 + 8*TT + 2*tig + 1];
    }

    const float NEG = __int_as_float(0xff800000);
    float rmax[16];
    #pragma unroll
    for (int i = 0; i < 16; ++i) rmax[i] = NEG;
    float ajmin0 = 1e30f, ajmin1 = 1e30f;   // track any(adj==0) per row

    const uint32_t ldmb0 = sb + OFF_SA
        + (uint32_t)(m0 + ((lane >> 3) & 1)*8 + (lane & 7)) * 272u
        + (uint32_t)((lane >> 4) & 1) * 16u;

    // per-thread tile staging geometry: row = tid>>3, 16 floats at col (tid&7)*16
    const int srow = tid >> 3, scol = (tid & 7) * 16;
    const uint32_t sts_off = (uint32_t)srow*272u + (uint32_t)(tid & 7)*32u;
    const float* csall = reinterpret_cast<const float*>(smem + OFF_C);

    // ---- stage fp16 tile from registers ----
    auto sts_tile = [&](int slot_, float4 f0, float4 f1, float4 f2, float4 f3) {
        __half2 h0 = __floats2half2_rn(f0.x, f0.y), h1 = __floats2half2_rn(f0.z, f0.w);
        __half2 h2 = __floats2half2_rn(f1.x, f1.y), h3 = __floats2half2_rn(f1.z, f1.w);
        __half2 h4 = __floats2half2_rn(f2.x, f2.y), h5 = __floats2half2_rn(f2.z, f2.w);
        __half2 h6 = __floats2half2_rn(f3.x, f3.y), h7 = __floats2half2_rn(f3.z, f3.w);
        uint4 o0, o1;
        o0.x = *reinterpret_cast<uint32_t*>(&h0); o0.y = *reinterpret_cast<uint32_t*>(&h1);
        o0.z = *reinterpret_cast<uint32_t*>(&h2); o0.w = *reinterpret_cast<uint32_t*>(&h3);
        o1.x = *reinterpret_cast<uint32_t*>(&h4); o1.y = *reinterpret_cast<uint32_t*>(&h5);
        o1.z = *reinterpret_cast<uint32_t*>(&h6); o1.w = *reinterpret_cast<uint32_t*>(&h7);
        char* dst = smem + OFF_SA + slot_*HB + sts_off;
        *reinterpret_cast<uint4*>(dst)      = o0;
        *reinterpret_cast<uint4*>(dst + 16) = o1;
    };

    // ---- MMA + fused epilogue for one sender ----
    auto do_sender = [&](int j) {
        const float* cs = csall + (j & 7)*256;
        float acc[4][4] = {{0,0,0,0},{0,0,0,0},{0,0,0,0},{0,0,0,0}};
        float acct[4] = {0,0,0,0};
        const uint32_t ldmb = ldmb0 + (uint32_t)(j & 3)*(uint32_t)HB;
        #pragma unroll
        for (int ks = 0; ks < 8; ++ks) {
            uint32_t a0, a1, a2, a3;
            asm volatile("ldmatrix.sync.aligned.m8n8.x4.shared.b16 {%0,%1,%2,%3}, [%4];"
                         : "=r"(a0), "=r"(a1), "=r"(a2), "=r"(a3)
                         : "r"(ldmb + (uint32_t)ks*32u));
            #pragma unroll
            for (int t = 0; t < 4; ++t)
                MMA4(acc[t], a0, a1, a2, a3, Br[ks][t][0], Br[ks][t][1]);
            if (cg == 0) {
                uint32_t b0 = *reinterpret_cast<const uint32_t*>(&sWtri[g*136 + ks*16 + 2*tig]);
                uint32_t b1 = *reinterpret_cast<const uint32_t*>(&sWtri[g*136 + ks*16 + 2*tig + 8]);
                MMA4(acct, a0, a1, a2, a3, b0, b1);
            }
        }
        const float aj0 = cs[128 + m0 + g];
        const float aj1 = cs[128 + m0 + 8 + g];
        ajmin0 = fminf(ajmin0, aj0);
        ajmin1 = fminf(ajmin1, aj1);
        const bool b0r = aj0 > 0.5f, b1r = aj1 > 0.5f;
        #pragma unroll
        for (int t = 0; t < 4; ++t) {
            const int c = cg*32 + t*8 + 2*tig;
            float2 a2v = *reinterpret_cast<const float2*>(&cs[c]);
            float v0 = acc[t][0] + a2v.x, v1 = acc[t][1] + a2v.y;
            float v2 = acc[t][2] + a2v.x, v3 = acc[t][3] + a2v.y;
            if (b0r) { rmax[4*t+0] = fmaxf(rmax[4*t+0], v0);
                       rmax[4*t+1] = fmaxf(rmax[4*t+1], v1); }
            if (b1r) { rmax[4*t+2] = fmaxf(rmax[4*t+2], v2);
                       rmax[4*t+3] = fmaxf(rmax[4*t+3], v3); }
        }
        if (cg == 0) {
            const int x = x0 + j;
            const float q0 = cs[160 + 2*tig], q1 = cs[160 + 2*tig + 1];
            float2 o0, o1;
            o0.x = fmaxf(acct[0] + p1[0] + q0, 0.f);
            o0.y = fmaxf(acct[1] + p1[1] + q1, 0.f);
            o1.x = fmaxf(acct[2] + p1[2] + q0, 0.f);
            o1.y = fmaxf(acct[3] + p1[3] + q1, 0.f);
            float* tp = out_tri + (((size_t)b*NN + x)*NN + y0)*TT;
            __stcs(reinterpret_cast<float2*>(&tp[(m0 + g)*TT + 2*tig]),     o0);
            __stcs(reinterpret_cast<float2*>(&tp[(m0 + 8 + g)*TT + 2*tig]), o1);
        }
    };

    // ---- prologue: consts senders 0..3 (two groups), tiles 0,1 staged directly
    stage_consts(sb, x0,     tid, adjp, b, y0);
    stage_consts(sb, x0 + 1, tid, adjp, b, y0);
    CP_COMMIT();
    stage_consts(sb, x0 + 2, tid, adjp, b, y0);
    stage_consts(sb, x0 + 3, tid, adjp, b, y0);
    CP_COMMIT();
    #pragma unroll
    for (int j = 0; j < 2; ++j) {
        const float4* ep = reinterpret_cast<const float4*>(
            edge + (((size_t)b*NN + x0 + j)*NN + y0 + srow)*DD + scol);
        sts_tile(j, __ldcs(ep), __ldcs(ep + 1), __ldcs(ep + 2), __ldcs(ep + 3));
    }

    for (int p = 0; p < TJ/2; ++p) {
        const int j0 = 2*p, j1 = j0 + 1;
        CP_WAIT(1);                        // consts j0,j1 complete
        __syncthreads();                   // tiles j0,j1 STS visible
        const bool pf = (j0 + 2 < TJ);

        float4 f0, f1, f2, f3;
        if (pf) {
            const float4* ep = reinterpret_cast<const float4*>(
                edge + (((size_t)b*NN + x0 + j0 + 2)*NN + y0 + srow)*DD + scol);
            f0 = __ldcs(ep); f1 = __ldcs(ep + 1); f2 = __ldcs(ep + 2); f3 = __ldcs(ep + 3);
        }
        do_sender(j0);
        if (pf) sts_tile((j0 + 2) & 3, f0, f1, f2, f3);

        if (pf) {
            const float4* ep = reinterpret_cast<const float4*>(
                edge + (((size_t)b*NN + x0 + j1 + 2)*NN + y0 + srow)*DD + scol);
            f0 = __ldcs(ep); f1 = __ldcs(ep + 1); f2 = __ldcs(ep + 2); f3 = __ldcs(ep + 3);
        }
        do_sender(j1);
        if (pf) sts_tile((j1 + 2) & 3, f0, f1, f2, f3);

        // consts for senders j0+4, j1+4 (clamped at tail; slot distance-safe)
        int xa = j0 + 4; if (xa > TJ - 1) xa = TJ - 1;
        int xb = j1 + 4; if (xb > TJ - 1) xb = TJ - 1;
        stage_consts(sb, x0 + xa, tid, adjp, b, y0);
        stage_consts(sb, x0 + xb, tid, adjp, b, y0);
        CP_COMMIT();
    }

    // ---- write partial maxes: deferred A1 add + exact mask-zero handling ----
    {
        const float z0 = (ajmin0 < 0.5f) ? 0.f : NEG;   // masked entries contribute exactly 0
        const float z1 = (ajmin1 < 0.5f) ? 0.f : NEG;
        const size_t base = (((size_t)(b*JC + xc))*NN + y0 + m0 + g)*DD;
        #pragma unroll
        for (int t = 0; t < 4; ++t) {
            const int c = cg*32 + t*8 + 2*tig;
            float2 u0 = *reinterpret_cast<const float2*>(&sA1[(m0 + g)*132 + c]);
            float2 u1 = *reinterpret_cast<const float2*>(&sA1[(m0 + 8 + g)*132 + c]);
            float2 v0 = { fmaxf(rmax[4*t+0] + u0.x, z0), fmaxf(rmax[4*t+1] + u0.y, z0) };
            float2 v1 = { fmaxf(rmax[4*t+2] + u1.x, z1), fmaxf(rmax[4*t+3] + u1.y, z1) };
            __stcs(reinterpret_cast<float2*>(&d_pmax[base + c]),        v0);
            __stcs(reinterpret_cast<float2*>(&d_pmax[base + 8*DD + c]), v1);
        }
    }
}

// ---------------- final reduce + output linear -------------------------------
__global__ __launch_bounds__(128) void k_reduce(
    const float* __restrict__ Wo2, const float* __restrict__ bo2,
    float* __restrict__ out_ret)
{
    __shared__ float sM[4][128];
    const int tid = threadIdx.x;
    const int gr0 = blockIdx.x * 4;
    const int b = gr0 >> 9;
    {
        const int r = tid >> 5, q = tid & 31;
        const int y = (gr0 + r) & 511;
        float4 m = { __int_as_float(0xff800000), __int_as_float(0xff800000),
                     __int_as_float(0xff800000), __int_as_float(0xff800000) };
        #pragma unroll
        for (int xc = 0; xc < JC; ++xc) {
            float4 v = *reinterpret_cast<const float4*>(
                &d_pmax[(((size_t)(b*JC + xc))*NN + y)*DD + q*4]);
            m.x = fmaxf(m.x, v.x); m.y = fmaxf(m.y, v.y);
            m.z = fmaxf(m.z, v.z); m.w = fmaxf(m.w, v.w);
        }
        *reinterpret_cast<float4*>(&sM[r][q*4]) = m;
    }
    __syncthreads();
    #pragma unroll
    for (int i = 0; i < 4; ++i) {
        int idx = tid + i*128;
        int r = idx >> 7, d = idx & 127;
        int gid = gr0 + r;
        float s = 0.f;
        #pragma unroll 8
        for (int k = 0; k < 128; ++k) s = fmaf(sM[r][k], Wo2[k*DD + d], s);
        out_ret[(size_t)gid*DD + d] = d_O1[(size_t)gid*DD + d] + s + bo2[d];
    }
}

// ---------------- launch ------------------------------------------------------
extern "C" void kernel_launch(void* const* d_in, const int* in_sizes, int n_in,
                              void* d_out, int out_size)
{
    const float* node   = (const float*)d_in[0];
    const float* edge   = (const float*)d_in[1];
    const float* graph  = (const float*)d_in[2];
    const float* adj    = (const float*)d_in[3];
    const float* hidden = (const float*)d_in[4];
    const float* Wm1 = (const float*)d_in[5],  *bm1 = (const float*)d_in[6];
    const float* Wm2 = (const float*)d_in[7],  *bm2 = (const float*)d_in[8];
    const float* Wme = (const float*)d_in[9],  *bme = (const float*)d_in[10];
    const float* Wmg = (const float*)d_in[11], *bmg = (const float*)d_in[12];
    const float* Wo1 = (const float*)d_in[13], *bo1 = (const float*)d_in[14];
    const float* Wo2 = (const float*)d_in[15], *bo2 = (const float*)d_in[16];
    const float* Wt1 = (const float*)d_in[17], *bt1 = (const float*)d_in[18];
    const float* Wt2 = (const float*)d_in[19], *bt2 = (const float*)d_in[20];
    const float* Wte = (const float*)d_in[21], *bte = (const float*)d_in[22];
    const float* Wtg = (const float*)d_in[23], *btg = (const float*)d_in[24];

    float* out_ret = (float*)d_out;                   // [2,512,128]
    float* out_tri = out_ret + (size_t)BB*NN*DD;      // [2,512,512,8]

    k_node<<<BB*NN/4, 256>>>(node, hidden, graph, Wm1, bm1, Wm2, bm2,
                             Wo1, bo1, Wt1, bt1, Wt2, bt2,
                             bme, Wmg, bmg, Wtg, bte, btg);
    k_dummy<<<1, 32>>>();
    k_dummy<<<1, 32>>>();
    cudaFuncSetAttribute(k_edge, cudaFuncAttributeMaxDynamicSharedMemorySize, SMEM_EDGE);
    k_edge<<<dim3(JC, NN/TY, BB), 256, SMEM_EDGE>>>(edge, adj, Wme, Wte, out_tri);
    k_reduce<<<BB*NN/4, 128>>>(Wo2, bo2, out_ret);
}